// round 2
// baseline (speedup 1.0000x reference)
#include <cuda_runtime.h>
#include <math.h>

typedef unsigned long long u64;

// ---------- packed f32x2 helpers (FFMA2 is PTX-only on sm_103a) ----------
__device__ __forceinline__ u64 dup2(float v){
    u64 r; asm("mov.b64 %0, {%1, %1};" : "=l"(r) : "f"(v)); return r;
}
__device__ __forceinline__ u64 pk2(float lo, float hi){
    u64 r; asm("mov.b64 %0, {%1, %2};" : "=l"(r) : "f"(lo), "f"(hi)); return r;
}
__device__ __forceinline__ void upk2(u64 a, float &lo, float &hi){
    asm("mov.b64 {%0, %1}, %2;" : "=f"(lo), "=f"(hi) : "l"(a));
}
__device__ __forceinline__ u64 fma2(u64 a, u64 b, u64 c){
    u64 d; asm("fma.rn.f32x2 %0, %1, %2, %3;" : "=l"(d) : "l"(a), "l"(b), "l"(c)); return d;
}
__device__ __forceinline__ u64 lds2(const float* p){ return *reinterpret_cast<const u64*>(p); }

union V4 { uint4 q; u64 d[2]; };

// ---------- adjacency prologue ----------
__device__ float g_adj[576];

// edge_index may arrive as int32 (harness-narrowed) or int64. Detect at runtime:
// for int64 little-endian values in [0,24), every odd 32-bit word of the first
// 192 words is 0. For int32, odd words are random node ids.
__global__ void build_adj_kernel(const int* __restrict__ ei_raw){
    __shared__ float sdeg[24];
    __shared__ float sdinv[24];
    __shared__ float sA[576];
    __shared__ int ssrc[96], sdst[96];
    __shared__ int is64;
    int t = threadIdx.x;

    if (t == 0){
        int z = 1;
        #pragma unroll 1
        for (int i = 1; i < 192; i += 2)
            if (ei_raw[i] != 0){ z = 0; break; }
        is64 = z;
    }
    if (t < 24) sdeg[t] = 1.0f;          // self-loop
    if (t < 576) sA[t] = 0.0f;
    __syncthreads();

    if (t < 96){
        int s, d;
        if (is64){
            const long long* e = reinterpret_cast<const long long*>(ei_raw);
            s = (int)e[t]; d = (int)e[96 + t];
        } else {
            s = ei_raw[t]; d = ei_raw[96 + t];
        }
        s = min(max(s, 0), 23);
        d = min(max(d, 0), 23);
        ssrc[t] = s; sdst[t] = d;
        atomicAdd(&sdeg[d], 1.0f);
    }
    __syncthreads();
    if (t < 24) sdinv[t] = 1.0f / sqrtf(sdeg[t]);
    __syncthreads();
    if (t < 96){
        int s = ssrc[t], d = sdst[t];
        atomicAdd(&sA[d*24 + s], sdinv[s]*sdinv[d]);   // duplicate edges accumulate
    }
    if (t < 24) atomicAdd(&sA[t*24 + t], sdinv[t]*sdinv[t]);
    __syncthreads();
    if (t < 576) g_adj[t] = sA[t];
}

// ---------- fused GCN + FC kernel ----------
#define NT 768
#define TB 32

// shared-memory float offsets
constexpr int SM_H   = 0;        // 32*24*32 = 24576 floats
constexpr int SM_WT  = 24576;    // 64*128  = 8192 floats (fcw1 tile; later overlaid by sfc1 32*129)
constexpr int SM_A   = 32768;    // 24*25   = 600
constexpr int SM_W   = 33368;    // 1012
constexpr int SM_B   = 34380;    // 88
constexpr int SM_FB1 = 34468;    // 128
constexpr int SM_FW2 = 34596;    // 256
constexpr int SM_FB2 = 34852;    // 2
constexpr int SMEM_FLOATS = 34856;
constexpr int SMEM_BYTES  = SMEM_FLOATS * 4;   // 139424 B

template<int FIN, int FOUT, bool STORE>
__device__ __forceinline__ void gcn_layer(float* h, const float* sWl, const float* sBl,
                                          const float* sArow, const float* smemHb, float* myrow)
{
    constexpr int KP = FOUT / 2;
    // ---- hw = h @ W (per-thread, W broadcast from shared) ----
    {
        u64 acc[KP];
        #pragma unroll
        for (int k = 0; k < KP; k++) acc[k] = 0ull;
        #pragma unroll
        for (int fi = 0; fi < FIN; fi++){
            u64 d = dup2(h[fi]);
            #pragma unroll
            for (int k = 0; k < KP; k += 2){
                V4 wv; wv.q = *reinterpret_cast<const uint4*>(sWl + fi*FOUT + 2*k);
                acc[k]   = fma2(d, wv.d[0], acc[k]);
                acc[k+1] = fma2(d, wv.d[1], acc[k+1]);
            }
        }
        #pragma unroll
        for (int k = 0; k < KP; k += 2){
            V4 o; o.d[0] = acc[k]; o.d[1] = acc[k+1];
            *reinterpret_cast<uint4*>(myrow + 2*k) = o.q;
        }
    }
    __syncthreads();
    // ---- aggregate: out = A[node,:] @ hw + bias ----
    u64 acc2[KP];
    #pragma unroll
    for (int k = 0; k < KP; k++) acc2[k] = lds2(sBl + 2*k);
    #pragma unroll 4
    for (int j = 0; j < 24; j++){
        u64 a2 = dup2(sArow[j]);
        const float* row = smemHb + j*32;
        #pragma unroll
        for (int k = 0; k < KP; k += 2){
            V4 v; v.q = *reinterpret_cast<const uint4*>(row + 2*k);
            acc2[k]   = fma2(a2, v.d[0], acc2[k]);
            acc2[k+1] = fma2(a2, v.d[1], acc2[k+1]);
        }
    }
    __syncthreads();
    // ---- relu ----
    if (STORE){
        #pragma unroll
        for (int k = 0; k < KP; k += 2){
            float a,b,c,d;
            upk2(acc2[k], a, b); upk2(acc2[k+1], c, d);
            V4 o;
            o.d[0] = pk2(fmaxf(a,0.f), fmaxf(b,0.f));
            o.d[1] = pk2(fmaxf(c,0.f), fmaxf(d,0.f));
            *reinterpret_cast<uint4*>(myrow + 2*k) = o.q;
        }
    } else {
        #pragma unroll
        for (int k = 0; k < KP; k++){
            float lo, hi; upk2(acc2[k], lo, hi);
            h[2*k]   = fmaxf(lo, 0.f);
            h[2*k+1] = fmaxf(hi, 0.f);
        }
    }
}

__global__ __launch_bounds__(NT, 1)
void gcn_fused_kernel(const float* __restrict__ x,
                      const float* __restrict__ W1, const float* __restrict__ b1,
                      const float* __restrict__ W2, const float* __restrict__ b2,
                      const float* __restrict__ W3, const float* __restrict__ b3,
                      const float* __restrict__ W4, const float* __restrict__ b4,
                      const float* __restrict__ W5, const float* __restrict__ b5,
                      const float* __restrict__ W6, const float* __restrict__ b6,
                      const float* __restrict__ W7, const float* __restrict__ b7,
                      const float* __restrict__ fcw1, const float* __restrict__ fcb1,
                      const float* __restrict__ fcw2, const float* __restrict__ fcb2,
                      float* __restrict__ out)
{
    extern __shared__ float sm[];
    float* smemH  = sm + SM_H;
    float* sWtile = sm + SM_WT;
    float* sfc1   = sm + SM_WT;    // overlay (32*129 <= 8192)
    float* sA     = sm + SM_A;
    float* sW     = sm + SM_W;
    float* sB     = sm + SM_B;
    float* sFcb1  = sm + SM_FB1;
    float* sFcw2  = sm + SM_FW2;
    float* sFcb2  = sm + SM_FB2;

    const int t = threadIdx.x;

    // ---- stage constants into shared ----
    if (t < 576) sA[(t/24)*25 + (t%24)] = g_adj[t];   // padded rows -> conflict-free A reads
    if (t < 4)   sW[0   + t] = W1[t];
    if (t < 16)  sW[4   + t] = W2[t];
    if (t < 32)  sW[20  + t] = W3[t];
    if (t < 64)  sW[52  + t] = W4[t];
    if (t < 128) sW[116 + t] = W5[t];
    if (t < 256) sW[244 + t] = W6[t];
    if (t < 512) sW[500 + t] = W7[t];
    if (t < 4)   sB[0  + t] = b1[t];
    if (t < 4)   sB[4  + t] = b2[t];
    if (t < 8)   sB[8  + t] = b3[t];
    if (t < 8)   sB[16 + t] = b4[t];
    if (t < 16)  sB[24 + t] = b5[t];
    if (t < 16)  sB[40 + t] = b6[t];
    if (t < 32)  sB[56 + t] = b7[t];
    if (t < 128) sFcb1[t] = fcb1[t];
    if (t < 256) sFcw2[t] = fcw2[t];
    if (t < 2)   sFcb2[t] = fcb2[t];

    // ---- GCN phase: thread = (b_local, node) ----
    const int b_local = t / 24;
    const int node    = t % 24;
    float* smemHb = smemH + b_local * 768;      // [24][32]
    float* myrow  = smemHb + node * 32;
    const float* sArow = sA + node * 25;

    float h[16];
    h[0] = x[blockIdx.x * 768 + t];             // x layout [B,24,1] -> coalesced
    __syncthreads();

    gcn_layer< 1,  4, false>(h, sW + 0,   sB + 0,  sArow, smemHb, myrow);
    gcn_layer< 4,  4, false>(h, sW + 4,   sB + 4,  sArow, smemHb, myrow);
    gcn_layer< 4,  8, false>(h, sW + 20,  sB + 8,  sArow, smemHb, myrow);
    gcn_layer< 8,  8, false>(h, sW + 52,  sB + 16, sArow, smemHb, myrow);
    gcn_layer< 8, 16, false>(h, sW + 116, sB + 24, sArow, smemHb, myrow);
    gcn_layer<16, 16, false>(h, sW + 244, sB + 40, sArow, smemHb, myrow);
    gcn_layer<16, 32, true >(h, sW + 500, sB + 56, sArow, smemHb, myrow);
    __syncthreads();   // smemH now holds h768 per batch (flat index = node*32 + f)

    // ---- FC1: [32 x 768] @ [768 x 128], register-tiled 4b x 4o, packed f32x2 ----
    const int warp = t >> 5;
    const int lane = t & 31;
    const int b0 = warp * 4;     // warps 0..7 cover 32 batches
    const int o0 = lane * 4;     // lanes cover 128 outputs
    u64 a0[4], a1[4];
    #pragma unroll
    for (int i = 0; i < 4; i++){ a0[i] = 0ull; a1[i] = 0ull; }

    for (int c = 0; c < 12; c++){
        // stage fcw1 rows [c*64, c*64+64) x 128 -> 32KB tile, coalesced float4
        const float4* srcv = reinterpret_cast<const float4*>(fcw1) + c * 2048;
        float4* dstv = reinterpret_cast<float4*>(sWtile);
        for (int i = t; i < 2048; i += NT) dstv[i] = srcv[i];
        __syncthreads();
        if (warp < 8){
            const float* hc = smemH + b0 * 768 + c * 64;
            #pragma unroll 4
            for (int f2 = 0; f2 < 32; f2++){
                const float* wr = sWtile + (f2 * 2) * 128 + o0;
                V4 wa, wb;
                wa.q = *reinterpret_cast<const uint4*>(wr);         // row f
                wb.q = *reinterpret_cast<const uint4*>(wr + 128);   // row f+1
                #pragma unroll
                for (int bb = 0; bb < 4; bb++){
                    u64 hp = lds2(hc + bb * 768 + f2 * 2);          // broadcast
                    float hx, hy; upk2(hp, hx, hy);
                    u64 d0 = dup2(hx), d1 = dup2(hy);
                    a0[bb] = fma2(d0, wa.d[0], a0[bb]);
                    a1[bb] = fma2(d0, wa.d[1], a1[bb]);
                    a0[bb] = fma2(d1, wb.d[0], a0[bb]);
                    a1[bb] = fma2(d1, wb.d[1], a1[bb]);
                }
            }
        }
        __syncthreads();
    }

    // ---- write fc1 (+bias) into padded shared (stride 129: conflict-free) ----
    if (warp < 8){
        #pragma unroll
        for (int bb = 0; bb < 4; bb++){
            float v0, v1, v2, v3;
            upk2(a0[bb], v0, v1);
            upk2(a1[bb], v2, v3);
            float* dst = sfc1 + (b0 + bb) * 129 + o0;
            dst[0] = v0 + sFcb1[o0];
            dst[1] = v1 + sFcb1[o0 + 1];
            dst[2] = v2 + sFcb1[o0 + 2];
            dst[3] = v3 + sFcb1[o0 + 3];
        }
    }
    __syncthreads();

    // ---- FC2 + log_softmax (2 classes) ----
    if (t < 32){
        const float* r = sfc1 + t * 129;
        float z0 = sFcb2[0], z1 = sFcb2[1];
        #pragma unroll 8
        for (int o = 0; o < 128; o++){
            float v = r[o];
            z0 += v * sFcw2[2*o];
            z1 += v * sFcw2[2*o + 1];
        }
        float m = fmaxf(z0, z1);
        float lse = m + logf(expf(z0 - m) + expf(z1 - m));
        int gb = blockIdx.x * 32 + t;
        out[gb * 2 + 0] = z0 - lse;
        out[gb * 2 + 1] = z1 - lse;
    }
}

// ---------- launch ----------
extern "C" void kernel_launch(void* const* d_in, const int* in_sizes, int n_in,
                              void* d_out, int out_size)
{
    const float* x    = (const float*)d_in[0];
    const int*   ei   = (const int*)d_in[1];     // dtype-agnostic; decoded on device
    const float* W1   = (const float*)d_in[2];
    const float* b1   = (const float*)d_in[3];
    const float* W2   = (const float*)d_in[4];
    const float* b2   = (const float*)d_in[5];
    const float* W3   = (const float*)d_in[6];
    const float* b3   = (const float*)d_in[7];
    const float* W4   = (const float*)d_in[8];
    const float* b4   = (const float*)d_in[9];
    const float* W5   = (const float*)d_in[10];
    const float* b5   = (const float*)d_in[11];
    const float* W6   = (const float*)d_in[12];
    const float* b6   = (const float*)d_in[13];
    const float* W7   = (const float*)d_in[14];
    const float* b7   = (const float*)d_in[15];
    const float* fcw1 = (const float*)d_in[16];
    const float* fcb1 = (const float*)d_in[17];
    const float* fcw2 = (const float*)d_in[18];
    const float* fcb2 = (const float*)d_in[19];
    float* out = (float*)d_out;

    const int B = in_sizes[0] / 24;     // x has 24 elements per batch (F0=1)
    const int grid = B / TB;            // 32768/32 = 1024

    cudaFuncSetAttribute(gcn_fused_kernel,
                         cudaFuncAttributeMaxDynamicSharedMemorySize, SMEM_BYTES);

    build_adj_kernel<<<1, 576>>>(ei);
    gcn_fused_kernel<<<grid, NT, SMEM_BYTES>>>(x,
        W1, b1, W2, b2, W3, b3, W4, b4, W5, b5, W6, b6, W7, b7,
        fcw1, fcb1, fcw2, fcb2, out);
}